// round 2
// baseline (speedup 1.0000x reference)
#include <cuda_runtime.h>

// SoftSplit: unfold(K=3,S=1,P=1) + Linear(576 -> 96), implemented as an
// implicit-GEMM 3x3 convolution.
//   x : (8, 64, 128, 128) f32
//   W : (96, 576) f32   (576 = c*9 + ki*3 + kj)
//   b : (96,) f32
//   out: (8, 16384, 96) f32,  out[b, r*128+c, n]

#define B_    8
#define C1    64
#define C2    96
#define HH    128
#define WW    128
#define CC    8            // input channels per k-chunk
#define KCH   (CC * 9)     // 72 k-values per chunk
#define NCHUNK (C1 / CC)   // 8 chunks

// W transposed to (576, 96) so chunk loads are flat contiguous copies.
__device__ float g_Wt[576 * C2];

__global__ void transpose_W_kernel(const float* __restrict__ W) {
    int idx = blockIdx.x * 256 + threadIdx.x;
    if (idx < C2 * 576) {
        int n = idx / 576;
        int k = idx - n * 576;
        g_Wt[k * C2 + n] = W[idx];
    }
}

__global__ __launch_bounds__(256, 2)
void softsplit_conv_kernel(const float* __restrict__ x,
                           const float* __restrict__ bias,
                           float* __restrict__ out) {
    // One block = one (batch, row): 128 output pixels x 96 channels.
    const int bidx = blockIdx.x;
    const int bb   = bidx >> 7;        // batch
    const int row  = bidx & 127;       // output row

    const int tid = threadIdx.x;
    const int ny  = tid & 7;           // 8 groups along N
    const int py  = tid >> 3;          // 32 groups along pixels
    const int n0  = ny * 12;           // 12 output channels per thread
    const int p0  = py * 4;            // 4 pixels per thread

    // Staged tiles.
    __shared__ float As[CC][3][132];       // [chan][row-1..row+1][col -1..129 (+pad)]
    __shared__ float Ws[KCH][C2];          // [k within chunk][n]

    float acc[4][12];
#pragma unroll
    for (int i = 0; i < 4; i++)
#pragma unroll
        for (int j = 0; j < 12; j++) acc[i][j] = 0.f;

    const float* xb = x + (size_t)bb * C1 * HH * WW;

    for (int ci = 0; ci < NCHUNK; ci++) {
        const int c0  = ci * CC;
        const int kg0 = c0 * 9;

        // ---- stage x tile (8 ch x 3 rows x 130 cols, zero-padded) ----
        for (int idx = tid; idx < CC * 3 * 132; idx += 256) {
            int cc  = idx / 396;
            int rem = idx - cc * 396;
            int rr  = rem / 132;
            int col = rem - rr * 132;
            int gr  = row - 1 + rr;
            int gc  = col - 1;
            float v = 0.f;
            if ((unsigned)gr < (unsigned)HH && (unsigned)gc < (unsigned)WW)
                v = xb[((c0 + cc) * HH + gr) * WW + gc];
            As[cc][rr][col] = v;
        }

        // ---- stage W slab: rows kg0..kg0+71 of Wt, flat contiguous copy ----
        {
            const float4* src = (const float4*)(g_Wt + (size_t)kg0 * C2);
            float4*       dst = (float4*)&Ws[0][0];
            for (int idx = tid; idx < (KCH * C2) / 4; idx += 256)
                dst[idx] = src[idx];
        }
        __syncthreads();

        // ---- compute: 72 k-steps, 48 FMA each per thread ----
#pragma unroll 1
        for (int cc = 0; cc < CC; cc++) {
#pragma unroll
            for (int rr = 0; rr < 3; rr++) {
                // 6-wide window of A covering pixels p0..p0+3 for taps dx=0..2
                float a6[6];
                {
                    const float4 av  = *(const float4*)&As[cc][rr][p0];
                    const float2 av2 = *(const float2*)&As[cc][rr][p0 + 4];
                    a6[0] = av.x; a6[1] = av.y; a6[2] = av.z; a6[3] = av.w;
                    a6[4] = av2.x; a6[5] = av2.y;
                }
#pragma unroll
                for (int dx = 0; dx < 3; dx++) {
                    const int kl = cc * 9 + rr * 3 + dx;
                    float w12[12];
                    {
                        const float4 w0 = *(const float4*)&Ws[kl][n0];
                        const float4 w1 = *(const float4*)&Ws[kl][n0 + 4];
                        const float4 w2 = *(const float4*)&Ws[kl][n0 + 8];
                        w12[0] = w0.x; w12[1] = w0.y; w12[2]  = w0.z; w12[3]  = w0.w;
                        w12[4] = w1.x; w12[5] = w1.y; w12[6]  = w1.z; w12[7]  = w1.w;
                        w12[8] = w2.x; w12[9] = w2.y; w12[10] = w2.z; w12[11] = w2.w;
                    }
#pragma unroll
                    for (int pi = 0; pi < 4; pi++) {
                        const float a = a6[pi + dx];
#pragma unroll
                        for (int nj = 0; nj < 12; nj++)
                            acc[pi][nj] += a * w12[nj];
                    }
                }
            }
        }
        __syncthreads();
    }

    // ---- epilogue: add bias, write (B, 16384, 96) ----
    float bv[12];
    {
        const float4 b0 = *(const float4*)(bias + n0);
        const float4 b1 = *(const float4*)(bias + n0 + 4);
        const float4 b2 = *(const float4*)(bias + n0 + 8);
        bv[0] = b0.x; bv[1] = b0.y; bv[2]  = b0.z; bv[3]  = b0.w;
        bv[4] = b1.x; bv[5] = b1.y; bv[6]  = b1.z; bv[7]  = b1.w;
        bv[8] = b2.x; bv[9] = b2.y; bv[10] = b2.z; bv[11] = b2.w;
    }

#pragma unroll
    for (int pi = 0; pi < 4; pi++) {
        const int pixel = p0 + pi;
        float* o = out + ((size_t)(bb * (HH * WW) + row * WW + pixel)) * C2 + n0;
        float4 o0, o1, o2;
        o0.x = acc[pi][0] + bv[0];  o0.y = acc[pi][1] + bv[1];
        o0.z = acc[pi][2] + bv[2];  o0.w = acc[pi][3] + bv[3];
        o1.x = acc[pi][4] + bv[4];  o1.y = acc[pi][5] + bv[5];
        o1.z = acc[pi][6] + bv[6];  o1.w = acc[pi][7] + bv[7];
        o2.x = acc[pi][8] + bv[8];  o2.y = acc[pi][9] + bv[9];
        o2.z = acc[pi][10] + bv[10]; o2.w = acc[pi][11] + bv[11];
        *(float4*)(o + 0) = o0;
        *(float4*)(o + 4) = o1;
        *(float4*)(o + 8) = o2;
    }
}

extern "C" void kernel_launch(void* const* d_in, const int* in_sizes, int n_in,
                              void* d_out, int out_size) {
    const float* x = (const float*)d_in[0];   // (8,64,128,128)
    const float* W = (const float*)d_in[1];   // (96,576)
    const float* b = (const float*)d_in[2];   // (96,)
    float* out = (float*)d_out;               // (8,16384,96)

    transpose_W_kernel<<<(C2 * 576 + 255) / 256, 256>>>(W);
    softsplit_conv_kernel<<<B_ * HH, 256>>>(x, b, out);
}

// round 4
// speedup vs baseline: 1.8019x; 1.8019x over previous
#include <cuda_runtime.h>

// SoftSplit: unfold(K=3,S=1,P=1) + Linear(576 -> 96) == implicit-GEMM 3x3 conv.
//   x : (8, 64, 128, 128) f32
//   W : (96, 576) f32   (576 = c*9 + ki*3 + kj)
//   b : (96,) f32
//   out: (8, 16384, 96) f32
//
// R2: packed f32x2 FMA path (fma.rn.f32x2) — 24 FFMA2 per k-step instead of
// 48 FFMA (FFMA-3reg is half-rate on sm_103a: rt_SMSP=2), halving FMA issue
// slots and doubling per-issue FLOP.

#define B_    8
#define C1    64
#define C2    96
#define HH    128
#define WW    128
#define CC    8            // input channels per k-chunk
#define KCH   (CC * 9)     // 72 k-values per chunk
#define NCHUNK (C1 / CC)   // 8 chunks

typedef unsigned long long ull;

#define FMA_F32X2(d, a, b) \
    asm("fma.rn.f32x2 %0, %1, %2, %0;" : "+l"(d) : "l"(a), "l"(b))
#define PACK_DUP_F32X2(d, s) \
    asm("mov.b64 %0, {%1, %1};" : "=l"(d) : "f"(s))

// W transposed to (576, 96) so chunk loads are flat contiguous copies.
__device__ float g_Wt[576 * C2];

__global__ void transpose_W_kernel(const float* __restrict__ W) {
    int idx = blockIdx.x * 256 + threadIdx.x;
    if (idx < C2 * 576) {
        int n = idx / 576;
        int k = idx - n * 576;
        g_Wt[k * C2 + n] = W[idx];
    }
}

__global__ __launch_bounds__(256, 2)
void softsplit_conv_kernel(const float* __restrict__ x,
                           const float* __restrict__ bias,
                           float* __restrict__ out) {
    // One block = one (batch, row): 128 output pixels x 96 channels.
    const int bidx = blockIdx.x;
    const int bb   = bidx >> 7;        // batch
    const int row  = bidx & 127;       // output row

    const int tid = threadIdx.x;
    const int ny  = tid & 7;           // 8 groups along N
    const int py  = tid >> 3;          // 32 groups along pixels
    const int n0  = ny * 12;           // 12 output channels per thread (6 pairs)
    const int p0  = py * 4;            // 4 pixels per thread

    __shared__ float As[CC][3][132];   // [chan][row-1..row+1][col -1..129 (+pad)]
    __shared__ float Ws[KCH][C2];      // [k within chunk][n]

    // 4 pixels x 6 channel-pairs of f32x2 accumulators.
    ull acc[4][6];
#pragma unroll
    for (int i = 0; i < 4; i++)
#pragma unroll
        for (int j = 0; j < 6; j++) acc[i][j] = 0ull;

    const float* xb = x + (size_t)bb * C1 * HH * WW;

    for (int ci = 0; ci < NCHUNK; ci++) {
        const int c0  = ci * CC;
        const int kg0 = c0 * 9;

        // ---- stage x tile (8 ch x 3 rows x 130 cols, zero-padded) ----
        for (int idx = tid; idx < CC * 3 * 132; idx += 256) {
            int cc  = idx / 396;
            int rem = idx - cc * 396;
            int rr  = rem / 132;
            int col = rem - rr * 132;
            int gr  = row - 1 + rr;
            int gc  = col - 1;
            float v = 0.f;
            if ((unsigned)gr < (unsigned)HH && (unsigned)gc < (unsigned)WW)
                v = xb[((c0 + cc) * HH + gr) * WW + gc];
            As[cc][rr][col] = v;
        }

        // ---- stage W slab: rows kg0..kg0+71 of Wt, flat contiguous copy ----
        {
            const float4* src = (const float4*)(g_Wt + (size_t)kg0 * C2);
            float4*       dst = (float4*)&Ws[0][0];
            for (int idx = tid; idx < (KCH * C2) / 4; idx += 256)
                dst[idx] = src[idx];
        }
        __syncthreads();

        // ---- compute ----
#pragma unroll 1
        for (int cc = 0; cc < CC; cc++) {
#pragma unroll
            for (int rr = 0; rr < 3; rr++) {
                // 6-wide A window for pixels p0..p0+3 over taps dx=0..2,
                // each value pre-duplicated into both halves of a 64-bit pair.
                ull apk[6];
                {
                    const float4 av  = *(const float4*)&As[cc][rr][p0];
                    const float2 av2 = *(const float2*)&As[cc][rr][p0 + 4];
                    PACK_DUP_F32X2(apk[0], av.x);
                    PACK_DUP_F32X2(apk[1], av.y);
                    PACK_DUP_F32X2(apk[2], av.z);
                    PACK_DUP_F32X2(apk[3], av.w);
                    PACK_DUP_F32X2(apk[4], av2.x);
                    PACK_DUP_F32X2(apk[5], av2.y);
                }
#pragma unroll
                for (int dx = 0; dx < 3; dx++) {
                    const int kl = cc * 9 + rr * 3 + dx;
                    union { float4 v[3]; ull u[6]; } w;
                    w.v[0] = *(const float4*)&Ws[kl][n0];
                    w.v[1] = *(const float4*)&Ws[kl][n0 + 4];
                    w.v[2] = *(const float4*)&Ws[kl][n0 + 8];
#pragma unroll
                    for (int pi = 0; pi < 4; pi++) {
#pragma unroll
                        for (int j = 0; j < 6; j++)
                            FMA_F32X2(acc[pi][j], apk[pi + dx], w.u[j]);
                    }
                }
            }
        }
        __syncthreads();
    }

    // ---- epilogue: add bias, write (B, 16384, 96) ----
    union { float4 v[3]; float f[12]; } bv;
    bv.v[0] = *(const float4*)(bias + n0);
    bv.v[1] = *(const float4*)(bias + n0 + 4);
    bv.v[2] = *(const float4*)(bias + n0 + 8);

#pragma unroll
    for (int pi = 0; pi < 4; pi++) {
        const int pixel = p0 + pi;
        float* o = out + ((size_t)(bb * (HH * WW) + row * WW + pixel)) * C2 + n0;
        union { ull u[6]; float f[12]; float4 v[3]; } r;
#pragma unroll
        for (int j = 0; j < 6; j++) r.u[j] = acc[pi][j];
#pragma unroll
        for (int j = 0; j < 12; j++) r.f[j] += bv.f[j];
        *(float4*)(o + 0) = r.v[0];
        *(float4*)(o + 4) = r.v[1];
        *(float4*)(o + 8) = r.v[2];
    }
}

extern "C" void kernel_launch(void* const* d_in, const int* in_sizes, int n_in,
                              void* d_out, int out_size) {
    const float* x = (const float*)d_in[0];   // (8,64,128,128)
    const float* W = (const float*)d_in[1];   // (96,576)
    const float* b = (const float*)d_in[2];   // (96,)
    float* out = (float*)d_out;               // (8,16384,96)

    transpose_W_kernel<<<(C2 * 576 + 255) / 256, 256>>>(W);
    softsplit_conv_kernel<<<B_ * HH, 256>>>(x, b, out);
}

// round 7
// speedup vs baseline: 2.6969x; 1.4967x over previous
#include <cuda_runtime.h>
#include <cuda_bf16.h>
#include <cstdint>

// SoftSplit: unfold(K=3,S=1,P=1) + Linear(576->96) as bf16-split implicit GEMM
// using family-portable tensor-core PTX (mma.sync.m16n8k16 + ldmatrix).
//   x : (8, 64, 128, 128) f32   W : (96, 576) f32   b : (96,)   out: (8,16384,96) f32
// D[m,n] = sum_k A[m,k] B[n,k];  a=a_hi+a_lo, b=b_hi+b_lo (bf16);
// D ≈ Ah*Bh + Ah*Bl + Al*Bh  accumulated in fp32 (lo*lo dropped, ~1e-5 rel).

#define B_    8
#define C1    64
#define C2    96
#define HH    128
#define WW    128
#define KTOT  576
#define NSLICE 9
#define KSL   64

typedef unsigned short u16;
typedef unsigned int   u32;

// ---------------- device scratch ----------------
__device__ u32 g_xpk[B_ * C1 * HH * WW];     // per x elem: bf16 hi | lo<<16
__device__ u16 g_Wb[NSLICE * 2 * C2 * KSL];  // per-slice SW128-swizzled [n][k] hi|lo slabs

__device__ __forceinline__ u32 smem_u32(const void* p) {
    u32 a;
    asm("{ .reg .u64 t; cvta.to.shared.u64 t, %1; cvt.u32.u64 %0, t; }"
        : "=r"(a) : "l"(p));
    return a;
}

#define LDSM_X4(r, a)                                                          \
    asm volatile("ldmatrix.sync.aligned.m8n8.x4.shared.b16 {%0,%1,%2,%3}, [%4];" \
        : "=r"((r)[0]), "=r"((r)[1]), "=r"((r)[2]), "=r"((r)[3]) : "r"(a))

#define MMA16816(d, a, b0, b1)                                                 \
    asm volatile("mma.sync.aligned.m16n8k16.row.col.f32.bf16.bf16.f32 "        \
        "{%0,%1,%2,%3}, {%4,%5,%6,%7}, {%8,%9}, {%0,%1,%2,%3};"                \
        : "+f"((d)[0]), "+f"((d)[1]), "+f"((d)[2]), "+f"((d)[3])               \
        : "r"((a)[0]), "r"((a)[1]), "r"((a)[2]), "r"((a)[3]), "r"(b0), "r"(b1))

// ---------------- prologue kernels ----------------
__global__ void pack_x_kernel(const float* __restrict__ x) {
    int i = blockIdx.x * 256 + threadIdx.x;
    if (i < B_ * C1 * HH * WW) {
        float v = x[i];
        __nv_bfloat16 h = __float2bfloat16(v);
        __nv_bfloat16 l = __float2bfloat16(v - __bfloat162float(h));
        g_xpk[i] = (u32)__bfloat16_as_ushort(h) | ((u32)__bfloat16_as_ushort(l) << 16);
    }
}

__global__ void pack_w_kernel(const float* __restrict__ W) {
    int i = blockIdx.x * 256 + threadIdx.x;          // NSLICE*C2*KSL = 55296
    if (i < NSLICE * C2 * KSL) {
        int s  = i / (C2 * KSL);
        int r  = i - s * (C2 * KSL);
        int n  = r / KSL;
        int kk = r - n * KSL;
        float v = W[n * KTOT + s * KSL + kk];
        __nv_bfloat16 h = __float2bfloat16(v);
        __nv_bfloat16 l = __float2bfloat16(v - __bfloat162float(h));
        u32 off = (u32)(n * 128 + kk * 2);
        u32 sw  = off ^ ((off >> 3) & 0x70);          // == off ^ ((n&7)<<4)
        g_Wb[(size_t)s * 12288 + (sw >> 1)]        = __bfloat16_as_ushort(h);
        g_Wb[(size_t)s * 12288 + 6144 + (sw >> 1)] = __bfloat16_as_ushort(l);
    }
}

// ---------------- main kernel ----------------
// smem: Ah 16384 | Al 16384 | Bh 12288 | Bl 12288 | bias 384  = 57,728 B
#define A_OFF   0
#define B_OFF   32768
#define BIAS_OFF 57344
#define SMEM_BYTES 57856

__global__ __launch_bounds__(256)
void softsplit_hmma_kernel(const float* __restrict__ bias,
                           float* __restrict__ out) {
    extern __shared__ char smem[];
    const u32 Su = smem_u32(smem);
    const u32 Au = Su + A_OFF;      // Ah; Al = Au + 16384
    const u32 Bu = Su + B_OFF;      // Bh; Bl = Bu + 12288
    float* bs = (float*)(smem + BIAS_OFF);

    const int bb  = blockIdx.x >> 7;
    const int row = blockIdx.x & 127;
    const int tid = threadIdx.x;
    const int wid = tid >> 5;
    const int lane = tid & 31;

    if (tid < C2) bs[tid] = bias[tid];

    // per-thread ldmatrix geometry
    const u32 xsw   = (u32)((lane & 7) << 4);                 // swizzle XOR
    const int m0    = wid << 4;
    const u32 aRow  = Au + (u32)((m0 + (lane & 15)) << 7);    // + k-term
    const u32 aKq   = (u32)(lane & 16);                       // 16 if k+8 quadrant
    const u32 bRowO = (u32)((((lane & 7) + ((lane >> 1) & 8))) << 7);
    const u32 bKq   = (u32)((lane & 8) << 1);                 // 16 if k+8 quadrant

    float acc[12][4];
#pragma unroll
    for (int t = 0; t < 12; ++t)
#pragma unroll
        for (int q = 0; q < 4; ++q) acc[t][q] = 0.f;

    const u32 xorv = xsw;   // for A staging (m&7 == lane&7)

    for (int s = 0; s < NSLICE; ++s) {
        __syncthreads();

        // ---- stage B slice (pre-swizzled, flat 24576 B copy) ----
        {
            const float4* src = (const float4*)(g_Wb + (size_t)s * 12288);
            float4* dst = (float4*)(smem + B_OFF);
#pragma unroll
            for (int i = 0; i < 6; ++i) dst[tid + 256 * i] = src[tid + 256 * i];
        }

        // ---- build A slice: [128 m][64 k] bf16 hi + lo, SW128 swizzled ----
#pragma unroll
        for (int it = 0; it < 4; ++it) {
            const int kk0 = (wid << 1) + (it << 4);  // even k pair
            const int k0 = s * KSL + kk0;
            const int k1 = k0 + 1;
            const int c0 = k0 / 9, t0 = k0 - 9 * c0;
            const int c1 = k1 / 9, t1 = k1 - 9 * c1;
            const int ki0 = t0 / 3, kj0 = t0 - 3 * ki0;
            const int ki1 = t1 / 3, kj1 = t1 - 3 * ki1;
            const int gr0 = row - 1 + ki0, gr1 = row - 1 + ki1;
            const bool ok0 = (unsigned)gr0 < (unsigned)HH;
            const bool ok1 = (unsigned)gr1 < (unsigned)HH;
            const u32* xr0 = g_xpk + (((size_t)(bb * C1 + c0) * HH + gr0) << 7);
            const u32* xr1 = g_xpk + (((size_t)(bb * C1 + c1) * HH + gr1) << 7);
            const u32 sb = ((u32)(kk0 << 1)) ^ xorv;
#pragma unroll
            for (int mi = 0; mi < 4; ++mi) {
                const int m = lane + (mi << 5);
                const int gc0 = m - 1 + kj0, gc1 = m - 1 + kj1;
                u32 v0 = (ok0 && (unsigned)gc0 < (unsigned)WW) ? xr0[gc0] : 0u;
                u32 v1 = (ok1 && (unsigned)gc1 < (unsigned)WW) ? xr1[gc1] : 0u;
                u32 hi = (v0 & 0xffffu) | (v1 << 16);
                u32 lo = (v0 >> 16)     | (v1 & 0xffff0000u);
                const u32 sw = ((u32)m << 7) + sb;
                *(u32*)(smem + A_OFF + sw)         = hi;
                *(u32*)(smem + A_OFF + 16384 + sw) = lo;
            }
        }

        __syncthreads();

        // ---- compute: 4 k-steps x 6 n16-groups x 3 products ----
#pragma unroll
        for (int ks = 0; ks < 4; ++ks) {
            u32 aH[4], aL[4];
            const u32 kaT = ((u32)(ks * 32) + aKq) ^ xsw;
            LDSM_X4(aH, aRow + kaT);
            LDSM_X4(aL, aRow + 16384 + kaT);
            const u32 kbT = ((u32)(ks * 32) + bKq) ^ xsw;
#pragma unroll
            for (int g = 0; g < 6; ++g) {
                const u32 ab = Bu + (u32)(g << 11) + bRowO + kbT;
                u32 bH[4], bL[4];
                LDSM_X4(bH, ab);
                MMA16816(acc[2 * g],     aH, bH[0], bH[1]);
                MMA16816(acc[2 * g + 1], aH, bH[2], bH[3]);
                LDSM_X4(bL, ab + 12288);
                MMA16816(acc[2 * g],     aH, bL[0], bL[1]);
                MMA16816(acc[2 * g + 1], aH, bL[2], bL[3]);
                MMA16816(acc[2 * g],     aL, bH[0], bH[1]);
                MMA16816(acc[2 * g + 1], aL, bH[2], bH[3]);
            }
        }
    }

    // ---- epilogue: D + bias -> out (8,16384,96) ----
    const int r  = lane >> 2;
    const int cb = (lane & 3) << 1;
    float* oro = out + ((size_t)(bb * (HH * WW) + (row << 7) + m0 + r)) * C2;
    float* or8 = oro + 8 * C2;
#pragma unroll
    for (int tt = 0; tt < 12; ++tt) {
        const int n = (tt << 3) + cb;
        float2 v0, v1;
        v0.x = acc[tt][0] + bs[n];     v0.y = acc[tt][1] + bs[n + 1];
        v1.x = acc[tt][2] + bs[n];     v1.y = acc[tt][3] + bs[n + 1];
        *(float2*)(oro + n) = v0;
        *(float2*)(or8 + n) = v1;
    }
}

extern "C" void kernel_launch(void* const* d_in, const int* in_sizes, int n_in,
                              void* d_out, int out_size) {
    const float* x = (const float*)d_in[0];   // (8,64,128,128)
    const float* W = (const float*)d_in[1];   // (96,576)
    const float* b = (const float*)d_in[2];   // (96,)
    float* out = (float*)d_out;               // (8,16384,96)

    cudaFuncSetAttribute(softsplit_hmma_kernel,
                         cudaFuncAttributeMaxDynamicSharedMemorySize, SMEM_BYTES);

    pack_x_kernel<<<(B_ * C1 * HH * WW + 255) / 256, 256>>>(x);
    pack_w_kernel<<<(NSLICE * C2 * KSL + 255) / 256, 256>>>(W);
    softsplit_hmma_kernel<<<B_ * HH, 256, SMEM_BYTES>>>(b, out);
}

// round 8
// speedup vs baseline: 4.0228x; 1.4916x over previous
#include <cuda_runtime.h>
#include <cuda_fp16.h>
#include <cstdint>

// SoftSplit: unfold(K=3,S=1,P=1) + Linear(576->96) as fp16 implicit GEMM
// (mma.sync.m16n8k16.f32.f16.f16.f32 + ldmatrix), fp32 accumulate.
//   x : (8, 64, 128, 128) f32   W : (96, 576) f32   b : (96,)   out: (8,16384,96) f32
// Precision: single fp16 operands; norm rel_err ~2-3e-4 < 1e-3 threshold.

#define B_    8
#define C1    64
#define C2    96
#define HH    128
#define WW    128
#define KTOT  576
#define NSLICE 9
#define KSL   64

typedef unsigned short u16;
typedef unsigned int   u32;

// per-slice SW128-swizzled [n][k] fp16 W slabs (12288 B each)
__device__ u16 g_Wh[NSLICE * C2 * KSL];

__device__ __forceinline__ u32 smem_u32(const void* p) {
    u32 a;
    asm("{ .reg .u64 t; cvta.to.shared.u64 t, %1; cvt.u32.u64 %0, t; }"
        : "=r"(a) : "l"(p));
    return a;
}

#define LDSM_X4(r, a)                                                          \
    asm volatile("ldmatrix.sync.aligned.m8n8.x4.shared.b16 {%0,%1,%2,%3}, [%4];" \
        : "=r"((r)[0]), "=r"((r)[1]), "=r"((r)[2]), "=r"((r)[3]) : "r"(a))

#define MMA16816(d, a, b0, b1)                                                 \
    asm volatile("mma.sync.aligned.m16n8k16.row.col.f32.f16.f16.f32 "          \
        "{%0,%1,%2,%3}, {%4,%5,%6,%7}, {%8,%9}, {%0,%1,%2,%3};"                \
        : "+f"((d)[0]), "+f"((d)[1]), "+f"((d)[2]), "+f"((d)[3])               \
        : "r"((a)[0]), "r"((a)[1]), "r"((a)[2]), "r"((a)[3]), "r"(b0), "r"(b1))

// pack v0 (low) and v1 (high) into one u32 of two fp16
#define CVT_F16X2(d, v0, v1) \
    asm("cvt.rn.f16x2.f32 %0, %1, %2;" : "=r"(d) : "f"(v1), "f"(v0))

// ---------------- prologue: swizzle W to fp16 slabs ----------------
__global__ void pack_w_kernel(const float* __restrict__ W) {
    int i = blockIdx.x * 256 + threadIdx.x;          // NSLICE*C2*KSL = 55296
    if (i < NSLICE * C2 * KSL) {
        int s  = i / (C2 * KSL);
        int r  = i - s * (C2 * KSL);
        int n  = r / KSL;
        int kk = r - n * KSL;
        float v = W[n * KTOT + s * KSL + kk];
        u32 off = (u32)(n * 128 + kk * 2);
        u32 sw  = off ^ ((off >> 3) & 0x70);
        g_Wh[(size_t)s * 6144 + (sw >> 1)] = __half_as_ushort(__float2half_rn(v));
    }
}

// ---------------- main kernel ----------------
// smem: A 16384 | B 12288 | bias 384  = 29,056 B
#define A_OFF    0
#define B_OFF    16384
#define BIAS_OFF 28672
#define SMEM_BYTES 29056

__global__ __launch_bounds__(256)
void softsplit_hmma_kernel(const float* __restrict__ x,
                           const float* __restrict__ bias,
                           float* __restrict__ out) {
    extern __shared__ char smem[];
    const u32 Su = smem_u32(smem);
    const u32 Au = Su + A_OFF;
    const u32 Bu = Su + B_OFF;
    float* bs = (float*)(smem + BIAS_OFF);

    const int bb  = blockIdx.x >> 7;
    const int row = blockIdx.x & 127;
    const int tid = threadIdx.x;
    const int wid = tid >> 5;
    const int lane = tid & 31;

    if (tid < C2) bs[tid] = bias[tid];

    // ldmatrix geometry
    const u32 xsw   = (u32)((lane & 7) << 4);                 // swizzle XOR
    const int m0    = wid << 4;
    const u32 aRow  = Au + (u32)((m0 + (lane & 15)) << 7);
    const u32 aKq   = (u32)(lane & 16);
    const u32 bRowO = (u32)((((lane & 7) + ((lane >> 1) & 8))) << 7);
    const u32 bKq   = (u32)((lane & 8) << 1);

    float acc[12][4];
#pragma unroll
    for (int t = 0; t < 12; ++t)
#pragma unroll
        for (int q = 0; q < 4; ++q) acc[t][q] = 0.f;

    for (int s = 0; s < NSLICE; ++s) {
        __syncthreads();

        // ---- stage B slice (pre-swizzled fp16 slab, flat 12288 B copy) ----
        {
            const float4* src = (const float4*)(g_Wh + (size_t)s * 6144);
            float4* dst = (float4*)(smem + B_OFF);
#pragma unroll
            for (int i = 0; i < 3; ++i) dst[tid + 256 * i] = src[tid + 256 * i];
        }

        // ---- build A slice: [128 m][64 k] fp16, SW128 swizzled, from x f32 ----
#pragma unroll
        for (int it = 0; it < 4; ++it) {
            const int kk0 = (wid << 1) + (it << 4);  // even k pair
            const int k0 = s * KSL + kk0;
            const int k1 = k0 + 1;
            const int c0 = k0 / 9, t0 = k0 - 9 * c0;
            const int c1 = k1 / 9, t1 = k1 - 9 * c1;
            const int ki0 = t0 / 3, kj0 = t0 - 3 * ki0;
            const int ki1 = t1 / 3, kj1 = t1 - 3 * ki1;
            const int gr0 = row - 1 + ki0, gr1 = row - 1 + ki1;
            const bool ok0 = (unsigned)gr0 < (unsigned)HH;
            const bool ok1 = (unsigned)gr1 < (unsigned)HH;
            const float* xr0 = x + (((size_t)(bb * C1 + c0) * HH + gr0) << 7);
            const float* xr1 = x + (((size_t)(bb * C1 + c1) * HH + gr1) << 7);
            const u32 sb = ((u32)(kk0 << 1)) ^ xsw;
#pragma unroll
            for (int mi = 0; mi < 4; ++mi) {
                const int m = lane + (mi << 5);
                const int gc0 = m - 1 + kj0, gc1 = m - 1 + kj1;
                float v0 = (ok0 && (unsigned)gc0 < (unsigned)WW) ? xr0[gc0] : 0.f;
                float v1 = (ok1 && (unsigned)gc1 < (unsigned)WW) ? xr1[gc1] : 0.f;
                u32 pk;
                CVT_F16X2(pk, v0, v1);
                *(u32*)(smem + A_OFF + (((u32)m << 7) + sb)) = pk;
            }
        }

        __syncthreads();

        // ---- compute: 4 k-steps x 6 n16-groups ----
#pragma unroll
        for (int ks = 0; ks < 4; ++ks) {
            u32 aF[4];
            LDSM_X4(aF, aRow + (((u32)(ks * 32) + aKq) ^ xsw));
            const u32 kbT = ((u32)(ks * 32) + bKq) ^ xsw;
#pragma unroll
            for (int g = 0; g < 6; ++g) {
                u32 bF[4];
                LDSM_X4(bF, Bu + (u32)(g << 11) + bRowO + kbT);
                MMA16816(acc[2 * g],     aF, bF[0], bF[1]);
                MMA16816(acc[2 * g + 1], aF, bF[2], bF[3]);
            }
        }
    }

    // ---- epilogue: D + bias -> out (8,16384,96) ----
    const int r  = lane >> 2;
    const int cb = (lane & 3) << 1;
    float* oro = out + ((size_t)(bb * (HH * WW) + (row << 7) + m0 + r)) * C2;
    float* or8 = oro + 8 * C2;
#pragma unroll
    for (int tt = 0; tt < 12; ++tt) {
        const int n = (tt << 3) + cb;
        float2 v0, v1;
        v0.x = acc[tt][0] + bs[n];     v0.y = acc[tt][1] + bs[n + 1];
        v1.x = acc[tt][2] + bs[n];     v1.y = acc[tt][3] + bs[n + 1];
        *(float2*)(oro + n) = v0;
        *(float2*)(or8 + n) = v1;
    }
}

extern "C" void kernel_launch(void* const* d_in, const int* in_sizes, int n_in,
                              void* d_out, int out_size) {
    const float* x = (const float*)d_in[0];   // (8,64,128,128)
    const float* W = (const float*)d_in[1];   // (96,576)
    const float* b = (const float*)d_in[2];   // (96,)
    float* out = (float*)d_out;               // (8,16384,96)

    pack_w_kernel<<<(NSLICE * C2 * KSL + 255) / 256, 256>>>(W);
    softsplit_hmma_kernel<<<B_ * HH, 256, SMEM_BYTES>>>(x, b, out);
}

// round 10
// speedup vs baseline: 6.3237x; 1.5720x over previous
#include <cuda_runtime.h>
#include <cuda_fp16.h>
#include <cstdint>

// SoftSplit: unfold(K=3,S=1,P=1) + Linear(576->96), fp16 implicit GEMM
// (mma.sync.m16n8k16 + ldmatrix), fp32 accumulate, pipelined A/B staging.
//   x : (8, 64, 128, 128) f32   W : (96, 576) f32   b : (96,)   out: (8,16384,96) f32

#define B_    8
#define C1    64
#define C2    96
#define HH    128
#define WW    128
#define KTOT  576
#define NSLICE 9
#define KSL   64
#define AROW  272                 // bytes per k-row of A tile (256 data + 16 pad)
#define ATILE (KSL * AROW)        // 17408
#define BTILE 12288

typedef unsigned short u16;
typedef unsigned int   u32;

#define A0_OFF   0
#define A1_OFF   ATILE
#define B0_OFF   (2 * ATILE)              // 34816 (mult of 128)
#define B1_OFF   (2 * ATILE + BTILE)      // 47104
#define BIAS_OFF (2 * ATILE + 2 * BTILE)  // 59392
#define SMEM_BYTES (BIAS_OFF + 384)       // 59776

// per-slice SW128-swizzled [n][k] fp16 W slabs (12288 B each)
__device__ u16 g_Wh[NSLICE * C2 * KSL];

__device__ __forceinline__ u32 smem_u32(const void* p) {
    u32 a;
    asm("{ .reg .u64 t; cvta.to.shared.u64 t, %1; cvt.u32.u64 %0, t; }"
        : "=r"(a) : "l"(p));
    return a;
}

#define LDSM_X4(r, a)                                                          \
    asm volatile("ldmatrix.sync.aligned.m8n8.x4.shared.b16 {%0,%1,%2,%3}, [%4];" \
        : "=r"((r)[0]), "=r"((r)[1]), "=r"((r)[2]), "=r"((r)[3]) : "r"(a))

#define LDSM_X4_T(r, a)                                                        \
    asm volatile("ldmatrix.sync.aligned.m8n8.x4.trans.shared.b16 {%0,%1,%2,%3}, [%4];" \
        : "=r"((r)[0]), "=r"((r)[1]), "=r"((r)[2]), "=r"((r)[3]) : "r"(a))

#define MMA16816(d, a, b0, b1)                                                 \
    asm volatile("mma.sync.aligned.m16n8k16.row.col.f32.f16.f16.f32 "          \
        "{%0,%1,%2,%3}, {%4,%5,%6,%7}, {%8,%9}, {%0,%1,%2,%3};"                \
        : "+f"((d)[0]), "+f"((d)[1]), "+f"((d)[2]), "+f"((d)[3])               \
        : "r"((a)[0]), "r"((a)[1]), "r"((a)[2]), "r"((a)[3]), "r"(b0), "r"(b1))

#define CVT_F16X2(d, v0, v1) \
    asm("cvt.rn.f16x2.f32 %0, %1, %2;" : "=r"(d) : "f"(v1), "f"(v0))

#define CP_ASYNC16(dst, src) \
    asm volatile("cp.async.cg.shared.global [%0], [%1], 16;" :: "r"(dst), "l"(src))
#define CP_COMMIT()  asm volatile("cp.async.commit_group;" ::: "memory")
#define CP_WAIT0()   asm volatile("cp.async.wait_group 0;" ::: "memory")

#define STS64(a, p0, p1) \
    asm volatile("st.shared.v2.b32 [%0], {%1, %2};" :: "r"(a), "r"(p0), "r"(p1))

// ---------------- prologue: swizzle W to fp16 slabs ----------------
__global__ void pack_w_kernel(const float* __restrict__ W) {
    int i = blockIdx.x * 256 + threadIdx.x;          // NSLICE*C2*KSL = 55296
    if (i < NSLICE * C2 * KSL) {
        int s  = i / (C2 * KSL);
        int r  = i - s * (C2 * KSL);
        int n  = r / KSL;
        int kk = r - n * KSL;
        float v = W[n * KTOT + s * KSL + kk];
        u32 off = (u32)(n * 128 + kk * 2);
        u32 sw  = off ^ ((off >> 3) & 0x70);
        g_Wh[(size_t)s * 6144 + (sw >> 1)] = __half_as_ushort(__float2half_rn(v));
    }
}

// ---------------- main kernel ----------------
__global__ __launch_bounds__(256, 2)
void softsplit_hmma_kernel(const float* __restrict__ x,
                           const float* __restrict__ bias,
                           float* __restrict__ out) {
    extern __shared__ char smem[];
    const u32 Su = smem_u32(smem);
    float* bs = (float*)(smem + BIAS_OFF);

    const int bb   = blockIdx.x >> 7;
    const int row  = blockIdx.x & 127;
    const int tid  = threadIdx.x;
    const int wid  = tid >> 5;
    const int lane = tid & 31;

    if (tid < C2) bs[tid] = bias[tid];

    const int m0 = wid << 4;
    // B-side ldmatrix geometry (SW128 swizzled slab, unchanged from R8)
    const u32 xsw   = (u32)((lane & 7) << 4);
    const u32 bRowO = (u32)((((lane & 7) + ((lane >> 1) & 8))) << 7);
    const u32 bKq   = (u32)((lane & 8) << 1);
    // A-side trans-ldmatrix: lanes 0-7:T0(k0-7,m0) 8-15:T1(k0-7,m0+8)
    //                        16-23:T2(k8-15,m0) 24-31:T3(k8-15,m0+8)
    const u32 aOff  = (u32)(((lane & 7) + ((lane & 16) >> 1)) * AROW
                            + ((m0 + (lane & 8)) << 1));

    float acc[12][4];
#pragma unroll
    for (int t = 0; t < 12; ++t)
#pragma unroll
        for (int q = 0; q < 4; ++q) acc[t][q] = 0.f;

    const float* xb = x + ((size_t)bb * C1 * HH * WW) + (lane << 2);

    // staged registers for A-build of one slice
    float4 q0[4], q1[4];
    u32 sa0[4];
    int kjv[4];   // kj0; kj1 derived: kj1 = (kj0<2)? kj0+1 : 0

    // ---- stage A slice ss into regs; targets Abuf ----
#define STAGE_A(ss, Abuf)                                                      \
    {                                                                          \
        _Pragma("unroll")                                                      \
        for (int it = 0; it < 4; ++it) {                                       \
            const int klocal = 2 * (it * 8 + wid);                             \
            const int k0 = (ss) * KSL + klocal;                                \
            const int c0 = k0 / 9, t0 = k0 - 9 * c0;                           \
            const int ki0 = t0 / 3, kj0 = t0 - 3 * ki0;                        \
            const int gr0 = row - 1 + ki0;                                     \
            const float4 z = {0.f, 0.f, 0.f, 0.f};                             \
            q0[it] = ((unsigned)gr0 < (unsigned)HH)                            \
                ? *(const float4*)(xb + (((size_t)c0 * HH + gr0) << 7)) : z;   \
            if (kj0 < 2) {                                                     \
                q1[it] = q0[it];                                               \
            } else {                                                           \
                const int k1 = k0 + 1;                                         \
                const int c1 = k1 / 9, t1 = k1 - 9 * c1;                       \
                const int ki1 = t1 / 3;                                        \
                const int gr1 = row - 1 + ki1;                                 \
                q1[it] = ((unsigned)gr1 < (unsigned)HH)                        \
                    ? *(const float4*)(xb + (((size_t)c1 * HH + gr1) << 7)) : z; \
            }                                                                  \
            sa0[it] = (Abuf) + (u32)(klocal * AROW) + (u32)(lane << 3);        \
            kjv[it] = kj0;                                                     \
        }                                                                      \
    }

    // ---- finish: shuffle halos, convert, store ----
#define FINISH_A()                                                             \
    {                                                                          \
        _Pragma("unroll")                                                      \
        for (int it = 0; it < 4; ++it) {                                       \
            const int kj0 = kjv[it];                                           \
            const int kj1 = (kj0 < 2) ? kj0 + 1 : 0;                           \
            float eL0 = __shfl_up_sync(0xffffffffu, q0[it].w, 1);              \
            float eR0 = __shfl_down_sync(0xffffffffu, q0[it].x, 1);            \
            if (lane == 0)  eL0 = 0.f;                                         \
            if (lane == 31) eR0 = 0.f;                                         \
            float eL1 = __shfl_up_sync(0xffffffffu, q1[it].w, 1);              \
            float eR1 = __shfl_down_sync(0xffffffffu, q1[it].x, 1);            \
            if (lane == 0)  eL1 = 0.f;                                         \
            if (lane == 31) eR1 = 0.f;                                         \
            float w0, w1, w2, w3;                                              \
            if (kj0 == 0)      { w0 = eL0;      w1 = q0[it].x; w2 = q0[it].y; w3 = q0[it].z; } \
            else if (kj0 == 1) { w0 = q0[it].x; w1 = q0[it].y; w2 = q0[it].z; w3 = q0[it].w; } \
            else               { w0 = q0[it].y; w1 = q0[it].z; w2 = q0[it].w; w3 = eR0; }      \
            u32 pa, pb;                                                        \
            CVT_F16X2(pa, w0, w1); CVT_F16X2(pb, w2, w3);                      \
            STS64(sa0[it], pa, pb);                                            \
            if (kj1 == 0)      { w0 = eL1;      w1 = q1[it].x; w2 = q1[it].y; w3 = q1[it].z; } \
            else if (kj1 == 1) { w0 = q1[it].x; w1 = q1[it].y; w2 = q1[it].z; w3 = q1[it].w; } \
            else               { w0 = q1[it].y; w1 = q1[it].z; w2 = q1[it].w; w3 = eR1; }      \
            CVT_F16X2(pa, w0, w1); CVT_F16X2(pb, w2, w3);                      \
            STS64(sa0[it] + AROW, pa, pb);                                     \
        }                                                                      \
    }

#define STAGE_B(ss, Bbuf)                                                      \
    {                                                                          \
        const char* src = (const char*)g_Wh + (size_t)(ss) * BTILE + (tid << 4); \
        _Pragma("unroll")                                                      \
        for (int i = 0; i < 3; ++i)                                            \
            CP_ASYNC16((Bbuf) + (u32)(tid << 4) + (u32)(i * 4096),             \
                       src + i * 4096);                                        \
    }

    // ---- prologue: slice 0 ----
    STAGE_B(0, Su + B0_OFF);
    CP_COMMIT();
    STAGE_A(0, Su + A0_OFF);
    FINISH_A();
    CP_WAIT0();
    __syncthreads();

    for (int s = 0; s < NSLICE; ++s) {
        const int p = s & 1;
        const u32 Ab = Su + (p ? A1_OFF : A0_OFF);
        const u32 Bb = Su + (p ? B1_OFF : B0_OFF);
        const u32 An = Su + (p ? A0_OFF : A1_OFF);
        const u32 Bn = Su + (p ? B0_OFF : B1_OFF);

        if (s + 1 < NSLICE) {
            STAGE_B(s + 1, Bn);
            CP_COMMIT();
            STAGE_A(s + 1, An);
        }

        // ---- compute slice s: 4 k-chunks x 6 n16-groups ----
#pragma unroll
        for (int ks = 0; ks < 4; ++ks) {
            u32 aF[4];
            LDSM_X4_T(aF, Ab + aOff + (u32)(ks * 16 * AROW));
            const u32 kbT = ((u32)(ks * 32) + bKq) ^ xsw;
#pragma unroll
            for (int g = 0; g < 6; ++g) {
                u32 bF[4];
                LDSM_X4(bF, Bb + (u32)(g << 11) + bRowO + kbT);
                MMA16816(acc[2 * g],     aF, bF[0], bF[1]);
                MMA16816(acc[2 * g + 1], aF, bF[2], bF[3]);
            }
        }

        if (s + 1 < NSLICE) {
            FINISH_A();
            CP_WAIT0();
        }
        __syncthreads();
    }

    // ---- epilogue: D + bias -> out (8,16384,96) ----
    const int r  = lane >> 2;
    const int cb = (lane & 3) << 1;
    float* oro = out + ((size_t)(bb * (HH * WW) + (row << 7) + m0 + r)) * C2;
    float* or8 = oro + 8 * C2;
#pragma unroll
    for (int tt = 0; tt < 12; ++tt) {
        const int n = (tt << 3) + cb;
        float2 v0, v1;
        v0.x = acc[tt][0] + bs[n];     v0.y = acc[tt][1] + bs[n + 1];
        v1.x = acc[tt][2] + bs[n];     v1.y = acc[tt][3] + bs[n + 1];
        *(float2*)(oro + n) = v0;
        *(float2*)(or8 + n) = v1;
    }
}

extern "C" void kernel_launch(void* const* d_in, const int* in_sizes, int n_in,
                              void* d_out, int out_size) {
    const float* x = (const float*)d_in[0];   // (8,64,128,128)
    const float* W = (const float*)d_in[1];   // (96,576)
    const float* b = (const float*)d_in[2];   // (96,)
    float* out = (float*)d_out;               // (8,16384,96)

    cudaFuncSetAttribute(softsplit_hmma_kernel,
                         cudaFuncAttributeMaxDynamicSharedMemorySize, SMEM_BYTES);

    pack_w_kernel<<<(NSLICE * C2 * KSL + 255) / 256, 256>>>(W);
    softsplit_hmma_kernel<<<B_ * HH, 256, SMEM_BYTES>>>(x, b, out);
}

// round 11
// speedup vs baseline: 7.5800x; 1.1987x over previous
#include <cuda_runtime.h>
#include <cuda_fp16.h>
#include <cstdint>

// SoftSplit: unfold(K=3,S=1,P=1) + Linear(576->96), fp16 implicit GEMM
// (mma.sync.m16n8k16 + ldmatrix), fp32 accumulate, pipelined A/B staging.
// R10: m32xn48 warp tiles (halve redundant B LDSM), deduped halo shuffles.
//   x : (8, 64, 128, 128) f32   W : (96, 576) f32   b : (96,)   out: (8,16384,96) f32

#define B_    8
#define C1    64
#define C2    96
#define HH    128
#define WW    128
#define KTOT  576
#define NSLICE 9
#define KSL   64
#define AROW  272                 // bytes per k-row of A tile (256 data + 16 pad)
#define ATILE (KSL * AROW)        // 17408
#define BTILE 12288

typedef unsigned short u16;
typedef unsigned int   u32;

#define A0_OFF   0
#define A1_OFF   ATILE
#define B0_OFF   (2 * ATILE)              // 34816 (mult of 128)
#define B1_OFF   (2 * ATILE + BTILE)      // 47104
#define BIAS_OFF (2 * ATILE + 2 * BTILE)  // 59392
#define SMEM_BYTES (BIAS_OFF + 384)       // 59776

// per-slice SW128-swizzled [n][k] fp16 W slabs (12288 B each)
__device__ u16 g_Wh[NSLICE * C2 * KSL];

__device__ __forceinline__ u32 smem_u32(const void* p) {
    u32 a;
    asm("{ .reg .u64 t; cvta.to.shared.u64 t, %1; cvt.u32.u64 %0, t; }"
        : "=r"(a) : "l"(p));
    return a;
}

#define LDSM_X4(r, a)                                                          \
    asm volatile("ldmatrix.sync.aligned.m8n8.x4.shared.b16 {%0,%1,%2,%3}, [%4];" \
        : "=r"((r)[0]), "=r"((r)[1]), "=r"((r)[2]), "=r"((r)[3]) : "r"(a))

#define LDSM_X4_T(r, a)                                                        \
    asm volatile("ldmatrix.sync.aligned.m8n8.x4.trans.shared.b16 {%0,%1,%2,%3}, [%4];" \
        : "=r"((r)[0]), "=r"((r)[1]), "=r"((r)[2]), "=r"((r)[3]) : "r"(a))

#define MMA16816(d, a, b0, b1)                                                 \
    asm volatile("mma.sync.aligned.m16n8k16.row.col.f32.f16.f16.f32 "          \
        "{%0,%1,%2,%3}, {%4,%5,%6,%7}, {%8,%9}, {%0,%1,%2,%3};"                \
        : "+f"((d)[0]), "+f"((d)[1]), "+f"((d)[2]), "+f"((d)[3])               \
        : "r"((a)[0]), "r"((a)[1]), "r"((a)[2]), "r"((a)[3]), "r"(b0), "r"(b1))

#define CVT_F16X2(d, v0, v1) \
    asm("cvt.rn.f16x2.f32 %0, %1, %2;" : "=r"(d) : "f"(v1), "f"(v0))

#define CP_ASYNC16(dst, src) \
    asm volatile("cp.async.cg.shared.global [%0], [%1], 16;" :: "r"(dst), "l"(src))
#define CP_COMMIT()  asm volatile("cp.async.commit_group;" ::: "memory")
#define CP_WAIT0()   asm volatile("cp.async.wait_group 0;" ::: "memory")

#define STS64(a, p0, p1) \
    asm volatile("st.shared.v2.b32 [%0], {%1, %2};" :: "r"(a), "r"(p0), "r"(p1))

// ---------------- prologue: swizzle W to fp16 slabs ----------------
__global__ void pack_w_kernel(const float* __restrict__ W) {
    int i = blockIdx.x * 256 + threadIdx.x;          // NSLICE*C2*KSL = 55296
    if (i < NSLICE * C2 * KSL) {
        int s  = i / (C2 * KSL);
        int r  = i - s * (C2 * KSL);
        int n  = r / KSL;
        int kk = r - n * KSL;
        float v = W[n * KTOT + s * KSL + kk];
        u32 off = (u32)(n * 128 + kk * 2);
        u32 sw  = off ^ ((off >> 3) & 0x70);
        g_Wh[(size_t)s * 6144 + (sw >> 1)] = __half_as_ushort(__float2half_rn(v));
    }
}

// ---------------- main kernel ----------------
__global__ __launch_bounds__(256, 2)
void softsplit_hmma_kernel(const float* __restrict__ x,
                           const float* __restrict__ bias,
                           float* __restrict__ out) {
    extern __shared__ char smem[];
    const u32 Su = smem_u32(smem);
    float* bs = (float*)(smem + BIAS_OFF);

    const int bb   = blockIdx.x >> 7;
    const int row  = blockIdx.x & 127;
    const int tid  = threadIdx.x;
    const int wid  = tid >> 5;
    const int lane = tid & 31;

    if (tid < C2) bs[tid] = bias[tid];

    // warp tile: m32 x n48.  4 m-groups x 2 n-halves.
    const int mw = (wid & 3) << 5;            // 0,32,64,96
    const int nw = (wid >> 2) * 48;           // 0 or 48
    const int gB = (wid >> 2) * 3;            // B n16-group base (0 or 3)

    // B-side ldmatrix geometry (SW128 swizzled slab)
    const u32 xsw   = (u32)((lane & 7) << 4);
    const u32 bRowO = (u32)((((lane & 7) + ((lane >> 1) & 8))) << 7);
    const u32 bKq   = (u32)((lane & 8) << 1);
    // A-side trans-ldmatrix base for m16 tile at column mw
    const u32 aOff  = (u32)(((lane & 7) + ((lane & 16) >> 1)) * AROW
                            + ((mw + (lane & 8)) << 1));

    // acc[a][j][q]: a = m16 half (0: mw, 1: mw+16), j = n8 tile (0..5)
    float acc[2][6][4];
#pragma unroll
    for (int a = 0; a < 2; ++a)
#pragma unroll
        for (int j = 0; j < 6; ++j)
#pragma unroll
            for (int q = 0; q < 4; ++q) acc[a][j][q] = 0.f;

    const float* xb = x + ((size_t)bb * C1 * HH * WW) + (lane << 2);

    // staged registers for A-build of one slice
    float4 q0[4], q1[4];
    u32 sa0[4];
    int kjv[4];   // kj0; kj1 = (kj0<2)? kj0+1 : 0

    // ---- stage A slice ss into regs; targets Abuf ----
#define STAGE_A(ss, Abuf)                                                      \
    {                                                                          \
        _Pragma("unroll")                                                      \
        for (int it = 0; it < 4; ++it) {                                       \
            const int klocal = 2 * (it * 8 + wid);                             \
            const int k0 = (ss) * KSL + klocal;                                \
            const int c0 = k0 / 9, t0 = k0 - 9 * c0;                           \
            const int ki0 = t0 / 3, kj0 = t0 - 3 * ki0;                        \
            const int gr0 = row - 1 + ki0;                                     \
            const float4 z = {0.f, 0.f, 0.f, 0.f};                             \
            q0[it] = ((unsigned)gr0 < (unsigned)HH)                            \
                ? *(const float4*)(xb + (((size_t)c0 * HH + gr0) << 7)) : z;   \
            if (kj0 == 2) {                                                    \
                const int k1 = k0 + 1;                                         \
                const int c1 = k1 / 9, t1 = k1 - 9 * c1;                       \
                const int ki1 = t1 / 3;                                        \
                const int gr1 = row - 1 + ki1;                                 \
                q1[it] = ((unsigned)gr1 < (unsigned)HH)                        \
                    ? *(const float4*)(xb + (((size_t)c1 * HH + gr1) << 7)) : z; \
            }                                                                  \
            sa0[it] = (Abuf) + (u32)(klocal * AROW) + (u32)(lane << 3);        \
            kjv[it] = kj0;                                                     \
        }                                                                      \
    }

    // ---- finish: minimal halo shuffles, convert, store both k-rows ----
#define FINISH_A()                                                             \
    {                                                                          \
        _Pragma("unroll")                                                      \
        for (int it = 0; it < 4; ++it) {                                       \
            const int kj0 = kjv[it];                                           \
            float w0, w1, w2, w3, u0, u1, u2, u3;                              \
            if (kj0 == 0) {                                                    \
                float eL = __shfl_up_sync(0xffffffffu, q0[it].w, 1);           \
                if (lane == 0) eL = 0.f;                                       \
                w0 = eL;        w1 = q0[it].x; w2 = q0[it].y; w3 = q0[it].z;   \
                u0 = q0[it].x;  u1 = q0[it].y; u2 = q0[it].z; u3 = q0[it].w;   \
            } else if (kj0 == 1) {                                             \
                float eR = __shfl_down_sync(0xffffffffu, q0[it].x, 1);         \
                if (lane == 31) eR = 0.f;                                      \
                w0 = q0[it].x;  w1 = q0[it].y; w2 = q0[it].z; w3 = q0[it].w;   \
                u0 = q0[it].y;  u1 = q0[it].z; u2 = q0[it].w; u3 = eR;         \
            } else {                                                           \
                float eR = __shfl_down_sync(0xffffffffu, q0[it].x, 1);         \
                if (lane == 31) eR = 0.f;                                      \
                float eL = __shfl_up_sync(0xffffffffu, q1[it].w, 1);           \
                if (lane == 0) eL = 0.f;                                       \
                w0 = q0[it].y;  w1 = q0[it].z; w2 = q0[it].w; w3 = eR;         \
                u0 = eL;        u1 = q1[it].x; u2 = q1[it].y; u3 = q1[it].z;   \
            }                                                                  \
            u32 pa, pb;                                                        \
            CVT_F16X2(pa, w0, w1); CVT_F16X2(pb, w2, w3);                      \
            STS64(sa0[it], pa, pb);                                            \
            CVT_F16X2(pa, u0, u1); CVT_F16X2(pb, u2, u3);                      \
            STS64(sa0[it] + AROW, pa, pb);                                     \
        }                                                                      \
    }

#define STAGE_B(ss, Bbuf)                                                      \
    {                                                                          \
        const char* src = (const char*)g_Wh + (size_t)(ss) * BTILE + (tid << 4); \
        _Pragma("unroll")                                                      \
        for (int i = 0; i < 3; ++i)                                            \
            CP_ASYNC16((Bbuf) + (u32)(tid << 4) + (u32)(i * 4096),             \
                       src + i * 4096);                                        \
    }

    // ---- prologue: slice 0 ----
    STAGE_B(0, Su + B0_OFF);
    CP_COMMIT();
    STAGE_A(0, Su + A0_OFF);
    FINISH_A();
    CP_WAIT0();
    __syncthreads();

    for (int s = 0; s < NSLICE; ++s) {
        const int p = s & 1;
        const u32 Ab = Su + (p ? A1_OFF : A0_OFF);
        const u32 Bb = Su + (p ? B1_OFF : B0_OFF);
        const u32 An = Su + (p ? A0_OFF : A1_OFF);
        const u32 Bn = Su + (p ? B0_OFF : B1_OFF);

        if (s + 1 < NSLICE) {
            STAGE_B(s + 1, Bn);
            CP_COMMIT();
            STAGE_A(s + 1, An);
        }

        // ---- compute slice s: 4 k-chunks; m32 x n48 per warp ----
#pragma unroll
        for (int ks = 0; ks < 4; ++ks) {
            u32 aF0[4], aF1[4];
            const u32 ka = Ab + aOff + (u32)(ks * 16 * AROW);
            LDSM_X4_T(aF0, ka);
            LDSM_X4_T(aF1, ka + 32);        // mw+16
            const u32 kbT = ((u32)(ks * 32) + bKq) ^ xsw;
#pragma unroll
            for (int g = 0; g < 3; ++g) {
                u32 bF[4];
                LDSM_X4(bF, Bb + (u32)((gB + g) << 11) + bRowO + kbT);
                MMA16816(acc[0][2 * g],     aF0, bF[0], bF[1]);
                MMA16816(acc[0][2 * g + 1], aF0, bF[2], bF[3]);
                MMA16816(acc[1][2 * g],     aF1, bF[0], bF[1]);
                MMA16816(acc[1][2 * g + 1], aF1, bF[2], bF[3]);
            }
        }

        if (s + 1 < NSLICE) {
            FINISH_A();
            CP_WAIT0();
        }
        __syncthreads();
    }

    // ---- epilogue: D + bias -> out (8,16384,96) ----
    const int r  = lane >> 2;
    const int cb = (lane & 3) << 1;
#pragma unroll
    for (int a = 0; a < 2; ++a) {
        const int mrow = mw + a * 16 + r;
        float* oro = out + ((size_t)(bb * (HH * WW) + (row << 7) + mrow)) * C2 + nw;
        float* or8 = oro + 8 * C2;
#pragma unroll
        for (int j = 0; j < 6; ++j) {
            const int n = (j << 3) + cb;
            float2 v0, v1;
            v0.x = acc[a][j][0] + bs[nw + n];     v0.y = acc[a][j][1] + bs[nw + n + 1];
            v1.x = acc[a][j][2] + bs[nw + n];     v1.y = acc[a][j][3] + bs[nw + n + 1];
            *(float2*)(oro + n) = v0;
            *(float2*)(or8 + n) = v1;
        }
    }
}

extern "C" void kernel_launch(void* const* d_in, const int* in_sizes, int n_in,
                              void* d_out, int out_size) {
    const float* x = (const float*)d_in[0];   // (8,64,128,128)
    const float* W = (const float*)d_in[1];   // (96,576)
    const float* b = (const float*)d_in[2];   // (96,)
    float* out = (float*)d_out;               // (8,16384,96)

    cudaFuncSetAttribute(softsplit_hmma_kernel,
                         cudaFuncAttributeMaxDynamicSharedMemorySize, SMEM_BYTES);

    pack_w_kernel<<<(NSLICE * C2 * KSL + 255) / 256, 256>>>(W);
    softsplit_hmma_kernel<<<B_ * HH, 256, SMEM_BYTES>>>(x, b, out);
}